// round 4
// baseline (speedup 1.0000x reference)
#include <cuda_runtime.h>
#include <stdint.h>

// Polar encoder, N=1024, K=512. Persistent kernel, one warp handles rows in a
// grid-stride loop, 2 rows per iteration (interleaved for MLP).
// Bit mapping: position p = j*128 + lane*4 + b <-> lane reg bit (4j+b).
// Stages on position bits {0,1,7,8,9} in-register; bits {2..6} via shfl_xor.

#define PN 1024
#define PK 512
#define WARPS_PER_CTA 8
#define CTA_THREADS (32 * WARPS_PER_CTA)
#define GRID_CTAS 912   // ~6 CTAs/SM on 152 SMs, single persistent wave

__device__ __forceinline__ unsigned nib(float4 v) {
    return (unsigned)(v.x != 0.0f)        | ((unsigned)(v.y != 0.0f) << 1) |
           ((unsigned)(v.z != 0.0f) << 2) | ((unsigned)(v.w != 0.0f) << 3);
}

__device__ __forceinline__ unsigned butterfly(unsigned x, int lane) {
    x ^= (x >> 1)  & 0x55555555u;   // s=0
    x ^= (x >> 2)  & 0x33333333u;   // s=1
    x ^= (x >> 4)  & 0x0f0f0f0fu;   // s=7
    x ^= (x >> 8)  & 0x00ff00ffu;   // s=8
    x ^= (x >> 16) & 0x0000ffffu;   // s=9
#pragma unroll
    for (int d = 1; d <= 16; d <<= 1) {           // s=2..6 (lane bits)
        unsigned y = __shfl_xor_sync(0xffffffffu, x, d);
        if ((lane & d) == 0) x ^= y;
    }
    return x;
}

__device__ __forceinline__ void store_row(float* __restrict__ out, int row,
                                          int lane, unsigned x) {
    float4* op = (float4*)(out + (size_t)row * PN);
#pragma unroll
    for (int j = 0; j < 8; j++) {
        unsigned n = x >> (4 * j);
        float4 f;
        f.x = __uint_as_float((n & 1u)        * 0x3f800000u);
        f.y = __uint_as_float(((n >> 1) & 1u) * 0x3f800000u);
        f.z = __uint_as_float(((n >> 2) & 1u) * 0x3f800000u);
        f.w = __uint_as_float(((n >> 3) & 1u) * 0x3f800000u);
        op[j * 32 + lane] = f;
    }
}

__global__ __launch_bounds__(CTA_THREADS)
void polar_encode_kernel(const float* __restrict__ u,
                         const int*   __restrict__ info_pos,
                         float* __restrict__ out,
                         int batch, int kcount) {
    const int tid  = threadIdx.x;
    const int lane = tid & 31;
    const int warp = tid >> 5;

    __shared__ int s_fast;
    __shared__ int s_inv[PN];                         // general path only
    __shared__ unsigned s_ubits[WARPS_PER_CTA][17];   // general path only

    // ---- per-CTA fast-layout check: kcount==512 && info_pos[k]==512+k ----
    if (tid == 0) s_fast = (kcount == PK) ? 1 : 0;
    __syncthreads();
    const int frozen = PN - kcount;
    for (int k = tid; k < kcount; k += CTA_THREADS) {
        if (info_pos[k] != frozen + k) s_fast = 0;    // benign race, all write 0
    }
    __syncthreads();
    const int fast = s_fast;

    if (!fast) {
        for (int i = tid; i < PN; i += CTA_THREADS) s_inv[i] = -1;
        __syncthreads();
        for (int k = tid; k < kcount; k += CTA_THREADS) s_inv[info_pos[k]] = k;
        __syncthreads();
    }

    const int gw = blockIdx.x * WARPS_PER_CTA + warp;  // global warp id
    const int tw = gridDim.x * WARPS_PER_CTA;          // total warps

    if (fast) {
        // info index k = i*128 + 4*lane + b -> p = 512+k -> reg bit 16+4i+b
        for (int r0 = gw; r0 < batch; r0 += 2 * tw) {
            const int r1 = r0 + tw;
            const bool ok1 = (r1 < batch);

            const float4* a4 = (const float4*)(u + (size_t)r0 * PK);
            float4 a0 = a4[lane],      a1 = a4[32 + lane];
            float4 a2 = a4[64 + lane], a3 = a4[96 + lane];

            unsigned x1 = 0u;
            if (ok1) {
                const float4* b4 = (const float4*)(u + (size_t)r1 * PK);
                float4 b0 = b4[lane],      b1 = b4[32 + lane];
                float4 b2 = b4[64 + lane], b3 = b4[96 + lane];
                x1 = (nib(b0) << 16) | (nib(b1) << 20) |
                     (nib(b2) << 24) | (nib(b3) << 28);
            }
            unsigned x0 = (nib(a0) << 16) | (nib(a1) << 20) |
                          (nib(a2) << 24) | (nib(a3) << 28);

            x0 = butterfly(x0, lane);
            if (ok1) x1 = butterfly(x1, lane);

            store_row(out, r0, lane, x0);
            if (ok1) store_row(out, r1, lane, x1);
        }
    } else {
        // general scatter: ballot-pack u, gather through inverse map
        for (int row = gw; row < batch; row += tw) {
            const float* up = u + (size_t)row * PK;
            const int nwords = (kcount + 31) >> 5;
            for (int j = 0; j < nwords; j++) {
                int idx = j * 32 + lane;
                float v = (idx < kcount) ? up[idx] : 0.0f;
                unsigned b = __ballot_sync(0xffffffffu, v != 0.0f);
                if (lane == j) s_ubits[warp][j & 15] = b;
            }
            __syncwarp();
            unsigned x = 0u;
#pragma unroll 4
            for (int r = 0; r < 32; r++) {
                int j = r >> 2, b = r & 3;
                int p = j * 128 + lane * 4 + b;
                int k = s_inv[p];
                if (k >= 0)
                    x |= ((s_ubits[warp][k >> 5] >> (k & 31)) & 1u) << r;
            }
            x = butterfly(x, lane);
            store_row(out, row, lane, x);
        }
    }
}

extern "C" void kernel_launch(void* const* d_in, const int* in_sizes, int n_in,
                              void* d_out, int out_size) {
    const float* u        = (const float*)d_in[0];
    const int*   info_pos = (const int*)d_in[1];
    // d_in[2] = ind_gather: butterfly structure fixed by N; unused.

    const int kcount = in_sizes[1];              // 512
    const int batch  = in_sizes[0] / kcount;     // 65536
    float* out = (float*)d_out;

    polar_encode_kernel<<<GRID_CTAS, CTA_THREADS>>>(u, info_pos, out,
                                                    batch, kcount);
}

// round 5
// speedup vs baseline: 1.1524x; 1.1524x over previous
#include <cuda_runtime.h>
#include <stdint.h>

// Polar encoder, N=1024, K=512. One warp per row (grid-per-row).
// Pack: 16x coalesced scalar loads + ballot (best measured DRAM%).
// Bit mapping: position p = j*128 + 4*lane + b <-> lane reg bit (4j+b),
// so the epilogue unpacks directly from the lane's own register (no shfl).
// Butterfly: position bits {0,1,7,8,9} in-register; {2..6} via shfl_xor.

#define PN 1024
#define PK 512
#define WARPS_PER_CTA 16
#define CTA_THREADS (32 * WARPS_PER_CTA)

__global__ __launch_bounds__(CTA_THREADS)
void polar_encode_kernel(const float* __restrict__ u,
                         const int*   __restrict__ info_pos,
                         float* __restrict__ out,
                         int batch, int kcount) {
    const int tid  = threadIdx.x;
    const int lane = tid & 31;
    const int warp = tid >> 5;
    const int row  = blockIdx.x * WARPS_PER_CTA + warp;

    __shared__ int s_fast;
    __shared__ int s_inv[PN];                          // general path only
    __shared__ unsigned s_ubits[WARPS_PER_CTA][17];    // 16 info words (+pad)

    // ---- per-CTA fast-layout check: kcount==512 && info_pos[k]==512+k ----
    if (tid == 0) s_fast = (kcount == PK) ? 1 : 0;
    __syncthreads();
    const int frozen = PN - kcount;
    if (tid < kcount) {                                // kcount<=512<CTA_THREADS
        if (info_pos[tid] != frozen + tid) s_fast = 0; // benign race
    }
    __syncthreads();
    const int fast = s_fast;

    if (!fast) {
        for (int i = tid; i < PN; i += CTA_THREADS) s_inv[i] = -1;
        __syncthreads();
        for (int k = tid; k < kcount; k += CTA_THREADS) s_inv[info_pos[k]] = k;
        __syncthreads();
    }

    if (row >= batch) return;

    const float* up = u + (size_t)row * PK;

    // ---- pack info bits: word j bit l = (u[row][32j+l] != 0) ----
    unsigned x = 0u;
    if (fast) {
#pragma unroll
        for (int j = 0; j < 16; j++) {
            float v = __ldcs(up + j * 32 + lane);
            unsigned b = __ballot_sync(0xffffffffu, v != 0.0f);
            if (lane == j) s_ubits[warp][j] = b;
        }
        __syncwarp();
        // reg bit r=16+4i+b <- info bit k = i*128 + 4*lane + b
        // word = 4i + (lane>>3), nibble at 4*(lane&7)
        const int wsel = lane >> 3;
        const int bsel = (lane & 7) * 4;
#pragma unroll
        for (int i = 0; i < 4; i++) {
            unsigned n = (s_ubits[warp][4 * i + wsel] >> bsel) & 0xfu;
            x |= n << (16 + 4 * i);
        }
    } else {
        const int nwords = (kcount + 31) >> 5;
        for (int j = 0; j < nwords; j++) {
            int idx = j * 32 + lane;
            float v = (idx < kcount) ? __ldcs(up + idx) : 0.0f;
            unsigned b = __ballot_sync(0xffffffffu, v != 0.0f);
            if (lane == j) s_ubits[warp][j & 15] = b;
        }
        __syncwarp();
#pragma unroll 4
        for (int r = 0; r < 32; r++) {
            int j = r >> 2, b = r & 3;
            int p = j * 128 + lane * 4 + b;
            int k = s_inv[p];
            if (k >= 0)
                x |= ((s_ubits[warp][k >> 5] >> (k & 31)) & 1u) << r;
        }
    }

    // ---- butterfly: in-register stages (position bits 0,1,7,8,9) ----
    x ^= (x >> 1)  & 0x55555555u;   // s=0
    x ^= (x >> 2)  & 0x33333333u;   // s=1
    x ^= (x >> 4)  & 0x0f0f0f0fu;   // s=7
    x ^= (x >> 8)  & 0x00ff00ffu;   // s=8
    x ^= (x >> 16) & 0x0000ffffu;   // s=9

    // ---- cross-lane stages (position bits 2..6 = lane bits) ----
#pragma unroll
    for (int d = 1; d <= 16; d <<= 1) {
        unsigned y = __shfl_xor_sync(0xffffffffu, x, d);
        if ((lane & d) == 0) x ^= y;
    }

    // ---- unpack: lane's reg bits 4j..4j+3 -> float4 at p = j*128+4*lane ----
    float4* op = (float4*)(out + (size_t)row * PN);
#pragma unroll
    for (int j = 0; j < 8; j++) {
        unsigned n = x >> (4 * j);
        float4 f;
        f.x = __uint_as_float((n & 1u)        * 0x3f800000u);
        f.y = __uint_as_float(((n >> 1) & 1u) * 0x3f800000u);
        f.z = __uint_as_float(((n >> 2) & 1u) * 0x3f800000u);
        f.w = __uint_as_float(((n >> 3) & 1u) * 0x3f800000u);
        __stcs(op + j * 32 + lane, f);
    }
}

extern "C" void kernel_launch(void* const* d_in, const int* in_sizes, int n_in,
                              void* d_out, int out_size) {
    const float* u        = (const float*)d_in[0];
    const int*   info_pos = (const int*)d_in[1];
    // d_in[2] = ind_gather: butterfly structure fixed by N; unused.

    const int kcount = in_sizes[1];              // 512
    const int batch  = in_sizes[0] / kcount;     // 65536
    float* out = (float*)d_out;

    int ctas = (batch + WARPS_PER_CTA - 1) / WARPS_PER_CTA;
    polar_encode_kernel<<<ctas, CTA_THREADS>>>(u, info_pos, out, batch, kcount);
}